// round 9
// baseline (speedup 1.0000x reference)
#include <cuda_runtime.h>
#include <math.h>

#define Bn 128
#define Dn 1024
#define Hn 256
#define Mn 100
#define Kn 5
#define MD 102400   // M*D

// ---------------- scratch (device globals; no runtime alloc) ----------------
__device__ float g_t1[Bn * 512];
__device__ float g_h1[Bn * 512];
__device__ float g_t2[Bn * 256];
__device__ float g_h2[Bn * 256];
__device__ float g_S1[12800 * 256];
__device__ int   g_idx[12800 * Kn];

#define NEG_INF __int_as_float(0xff800000)

// ---------------- packed f32x2 helpers ----------------
#define FMA2(d, a, b, c) \
    asm("fma.rn.f32x2 %0, %1, %2, %3;" : "=l"(d) : "l"(a), "l"(b), "l"(c))
#define PACK2(d, x) \
    asm("mov.b64 %0, {%1, %1};" : "=l"(d) : "r"(__float_as_uint(x)))

// =====================================================================
// K1: t1 = x[128,1024] @ gW1[1024,512] + gb1
// grid (32, 2), block 256.  4 batch rows per block, 256 cols per block.
// Inner accumulation: strict k-ascending FFMA chain per output.
// =====================================================================
__global__ __launch_bounds__(256) void k_gemm1(const float* __restrict__ x,
                                               const float* __restrict__ W,
                                               const float* __restrict__ bias)
{
    const int b0 = blockIdx.x << 2;
    const int j  = (blockIdx.y << 8) + threadIdx.x;
    __shared__ __align__(16) float xs[4][1024];
#pragma unroll
    for (int i = 0; i < 4; i++) {
        int idx = threadIdx.x + (i << 8);          // 0..1023 float4 slots
        int r = idx >> 8, k4 = idx & 255;
        *(float4*)&xs[r][k4 << 2] = *(const float4*)(x + (b0 + r) * 1024 + (k4 << 2));
    }
    __syncthreads();
    float acc0 = 0.f, acc1 = 0.f, acc2 = 0.f, acc3 = 0.f;
#pragma unroll 8
    for (int k = 0; k < 1024; k++) {
        float w = W[k * 512 + j];
        acc0 = fmaf(xs[0][k], w, acc0);
        acc1 = fmaf(xs[1][k], w, acc1);
        acc2 = fmaf(xs[2][k], w, acc2);
        acc3 = fmaf(xs[3][k], w, acc3);
    }
    float bb = bias[j];
    g_t1[(b0 + 0) * 512 + j] = acc0 + bb;
    g_t1[(b0 + 1) * 512 + j] = acc1 + bb;
    g_t1[(b0 + 2) * 512 + j] = acc2 + bb;
    g_t1[(b0 + 3) * 512 + j] = acc3 + bb;
}

// =====================================================================
// K2: t2 = h1[128,512] @ gW2[512,256] + gb2   grid 32, block 256
// =====================================================================
__global__ __launch_bounds__(256) void k_gemm2(const float* __restrict__ W,
                                               const float* __restrict__ bias)
{
    const int b0 = blockIdx.x << 2;
    const int j  = threadIdx.x;
    __shared__ __align__(16) float xs[4][512];
#pragma unroll
    for (int i = 0; i < 2; i++) {
        int idx = threadIdx.x + (i << 8);          // 0..511 float4 slots
        int r = idx >> 7, k4 = idx & 127;
        *(float4*)&xs[r][k4 << 2] = *(const float4*)(g_h1 + (b0 + r) * 512 + (k4 << 2));
    }
    __syncthreads();
    float acc0 = 0.f, acc1 = 0.f, acc2 = 0.f, acc3 = 0.f;
#pragma unroll 8
    for (int k = 0; k < 512; k++) {
        float w = W[k * 256 + j];
        acc0 = fmaf(xs[0][k], w, acc0);
        acc1 = fmaf(xs[1][k], w, acc1);
        acc2 = fmaf(xs[2][k], w, acc2);
        acc3 = fmaf(xs[3][k], w, acc3);
    }
    float bb = bias[j];
    g_t2[(b0 + 0) * 256 + j] = acc0 + bb;
    g_t2[(b0 + 1) * 256 + j] = acc1 + bb;
    g_t2[(b0 + 2) * 256 + j] = acc2 + bb;
    g_t2[(b0 + 3) * 256 + j] = acc3 + bb;
}

// ---------------- LN + ReLU (block per row, blockDim = n) ----------------
__device__ __forceinline__ void ln_relu_body(const float* tin, const float* sc,
                                             const float* bi, float* hout)
{
    const int n = blockDim.x;
    const int b = blockIdx.x, t = threadIdx.x;
    float v = tin[b * n + t];
    __shared__ float sr[16];
    float s = v;
#pragma unroll
    for (int o = 16; o; o >>= 1) s += __shfl_xor_sync(0xffffffffu, s, o);
    if ((t & 31) == 0) sr[t >> 5] = s;
    __syncthreads();
    const int nw = n >> 5;
    float tot = 0.f;
    for (int jj = 0; jj < nw; jj++) tot += sr[jj];
    float mu = tot / (float)n;
    float d = v - mu;
    __syncthreads();
    float q = d * d;
#pragma unroll
    for (int o = 16; o; o >>= 1) q += __shfl_xor_sync(0xffffffffu, q, o);
    if ((t & 31) == 0) sr[t >> 5] = q;
    __syncthreads();
    float tv = 0.f;
    for (int jj = 0; jj < nw; jj++) tv += sr[jj];
    float var = tv / (float)n;
    float hv = d * rsqrtf(var + 1e-5f) * sc[t] + bi[t];
    hout[b * n + t] = fmaxf(hv, 0.f);
}

__global__ void k_ln1(const float* __restrict__ sc, const float* __restrict__ bi)
{ ln_relu_body(g_t1, sc, bi, g_h1); }
__global__ void k_ln2(const float* __restrict__ sc, const float* __restrict__ bi)
{ ln_relu_body(g_t2, sc, bi, g_h2); }

// =====================================================================
// K3: logits = h2[128,256] @ gW3[256,102400] + gb3
// grid (8, 100): per block: full 128 batch rows x 128 cols of one m.
// 256 threads, 8x8 micro-tile, f32x2 FMAs, XOR-swizzled A tile.
// Accumulation is k-ascending per output (single FFMA chain).
// =====================================================================
__global__ __launch_bounds__(256) void k_gemm3(const float* __restrict__ W,
                                               const float* __restrict__ bias,
                                               float* __restrict__ out)
{
    const int m    = blockIdx.y;
    const int nb   = blockIdx.x << 7;
    const int col0 = m * 1024 + nb;
    __shared__ __align__(16) float As[32][128];   // As[k][b ^ (k&~3)]
    __shared__ __align__(16) float Bs[32][128];   // Bs[k][n]
    const int t = threadIdx.x;
    const int tx = t & 15, ty = t >> 4;

    unsigned long long acc[8][4];
#pragma unroll
    for (int r = 0; r < 8; r++)
#pragma unroll
        for (int c = 0; c < 4; c++) acc[r][c] = 0ULL;

    for (int kk = 0; kk < 256; kk += 32) {
#pragma unroll
        for (int i = 0; i < 4; i++) {           // A: 128 rows x 32 k
            int idx = t + (i << 8);
            int b = idx >> 3, k4 = idx & 7;
            float4 v = *(const float4*)(g_h2 + b * 256 + kk + (k4 << 2));
            int s = k4 << 2;
            int bc = b ^ s;
            As[s + 0][bc] = v.x;
            As[s + 1][bc] = v.y;
            As[s + 2][bc] = v.z;
            As[s + 3][bc] = v.w;
        }
#pragma unroll
        for (int i = 0; i < 4; i++) {           // B: 32 k x 128 n
            int idx = t + (i << 8);
            int k = idx >> 5, n4 = idx & 31;
            *(float4*)&Bs[k][n4 << 2] =
                *(const float4*)(W + (size_t)(kk + k) * MD + col0 + (n4 << 2));
        }
        __syncthreads();
#pragma unroll
        for (int k = 0; k < 32; k++) {
            const int s = k & ~3;
            const float4 a0 = *(const float4*)&As[k][(ty << 3) ^ s];
            const float4 a1 = *(const float4*)&As[k][((ty << 3) + 4) ^ s];
            const ulonglong2 b01 = *(const ulonglong2*)&Bs[k][tx << 3];
            const ulonglong2 b23 = *(const ulonglong2*)&Bs[k][(tx << 3) + 4];
            float av[8] = {a0.x, a0.y, a0.z, a0.w, a1.x, a1.y, a1.z, a1.w};
#pragma unroll
            for (int r = 0; r < 8; r++) {
                unsigned long long aa;
                PACK2(aa, av[r]);
                FMA2(acc[r][0], aa, b01.x, acc[r][0]);
                FMA2(acc[r][1], aa, b01.y, acc[r][1]);
                FMA2(acc[r][2], aa, b23.x, acc[r][2]);
                FMA2(acc[r][3], aa, b23.y, acc[r][3]);
            }
        }
        __syncthreads();
    }

    float bias0[8];
    const float* bp = bias + col0 + (tx << 3);
#pragma unroll
    for (int c = 0; c < 8; c++) bias0[c] = bp[c];
#pragma unroll
    for (int r = 0; r < 8; r++) {
        int b = (ty << 3) + r;
        float o[8];
#pragma unroll
        for (int c = 0; c < 4; c++) {
            unsigned long long u = acc[r][c];
            o[2 * c]     = __uint_as_float((unsigned)u) + bias0[2 * c];
            o[2 * c + 1] = __uint_as_float((unsigned)(u >> 32)) + bias0[2 * c + 1];
        }
        float4* dst = (float4*)(out + (size_t)b * MD + col0 + (tx << 3));
        dst[0] = make_float4(o[0], o[1], o[2], o[3]);
        dst[1] = make_float4(o[4], o[5], o[6], o[7]);
    }
}

// =====================================================================
// K4: per (b,m) row: probs = softmax(2*(logits+gumbel)); top-5 selected on
// RAW z = logits+gumbel (monotone-equivalent to ref's top_k on probs, and
// free of exp rounding noise in the tie path). grid 12800, block 256.
// =====================================================================
__global__ __launch_bounds__(256) void k_softmax_top5(const float* __restrict__ logits,
                                                      const float* __restrict__ gum,
                                                      float* __restrict__ probs)
{
    const int row = blockIdx.x;
    const int t = threadIdx.x;
    const float* lp = logits + (size_t)row * 1024;
    const float* gp = gum + (size_t)row * 1024;
    float zv[4];
#pragma unroll
    for (int i = 0; i < 4; i++) {
        int d = t + (i << 8);
        zv[i] = lp[d] + gp[d];                 // raw z (no tau scaling)
    }
    __shared__ float sred[8];
    float mx = fmaxf(fmaxf(zv[0], zv[1]), fmaxf(zv[2], zv[3]));
#pragma unroll
    for (int o = 16; o; o >>= 1) mx = fmaxf(mx, __shfl_xor_sync(0xffffffffu, mx, o));
    if ((t & 31) == 0) sred[t >> 5] = mx;
    __syncthreads();
    float rmax = sred[0];
#pragma unroll
    for (int j = 1; j < 8; j++) rmax = fmaxf(rmax, sred[j]);
    // exp(2*(z - zmax)) == exp(2z - 2zmax): *2 is exact and commutes with rounding
    float ev[4], lsum = 0.f;
#pragma unroll
    for (int i = 0; i < 4; i++) { ev[i] = __expf(2.0f * (zv[i] - rmax)); lsum += ev[i]; }
    __syncthreads();
#pragma unroll
    for (int o = 16; o; o >>= 1) lsum += __shfl_xor_sync(0xffffffffu, lsum, o);
    if ((t & 31) == 0) sred[t >> 5] = lsum;
    __syncthreads();
    float tot = 0.f;
#pragma unroll
    for (int j = 0; j < 8; j++) tot += sred[j];
    float inv = 1.0f / tot;
    int pd[4];
#pragma unroll
    for (int i = 0; i < 4; i++) {
        int d = t + (i << 8);
        pd[i] = d;
        probs[(size_t)row * 1024 + d] = ev[i] * inv;
    }
    // 5 rounds of block-wide argmax on z (tie-break: smaller index, like lax.top_k)
    __shared__ float swv[8];
    __shared__ int swi[8];
    __shared__ int s_wi;
#pragma unroll
    for (int r5 = 0; r5 < 5; r5++) {
        float bv = NEG_INF; int bi = 1 << 30;
#pragma unroll
        for (int i = 0; i < 4; i++)
            if (zv[i] > bv || (zv[i] == bv && pd[i] < bi)) { bv = zv[i]; bi = pd[i]; }
#pragma unroll
        for (int o = 16; o; o >>= 1) {
            float ov = __shfl_xor_sync(0xffffffffu, bv, o);
            int oi = __shfl_xor_sync(0xffffffffu, bi, o);
            if (ov > bv || (ov == bv && oi < bi)) { bv = ov; bi = oi; }
        }
        if ((t & 31) == 0) { swv[t >> 5] = bv; swi[t >> 5] = bi; }
        __syncthreads();
        if (t == 0) {
            float fv = swv[0]; int fi = swi[0];
#pragma unroll
            for (int j = 1; j < 8; j++)
                if (swv[j] > fv || (swv[j] == fv && swi[j] < fi)) { fv = swv[j]; fi = swi[j]; }
            s_wi = fi;
            g_idx[row * Kn + r5] = fi;
        }
        __syncthreads();
        int w = s_wi;
#pragma unroll
        for (int i = 0; i < 4; i++)
            if (pd[i] == w) zv[i] = NEG_INF;
    }
}

// =====================================================================
// K5: per (b,m): s1 = relu(gather sW1), y1 = relu(gather yW1),
//     synergy = tanh(y1 . yW2 + yb2).  S1 -> scratch.  grid 12800, block 256.
// =====================================================================
__global__ __launch_bounds__(256) void k_gather(const float* __restrict__ x,
                                                const float* __restrict__ sW1,
                                                const float* __restrict__ sb1,
                                                const float* __restrict__ yW1,
                                                const float* __restrict__ yb1,
                                                const float* __restrict__ yW2,
                                                const float* __restrict__ yb2,
                                                float* __restrict__ out_syn)
{
    const int row = blockIdx.x;
    const int t = threadIdx.x;
    __shared__ int si[5];
    __shared__ float sv[5];
    if (t < 5) {
        int id = g_idx[row * Kn + t];
        si[t] = id;
        sv[t] = x[(row / 100) * 1024 + id];
    }
    __syncthreads();
    float s1 = sb1[t], y1 = yb1[t];
#pragma unroll
    for (int j = 0; j < 5; j++) {
        int off = ((j << 10) + si[j]) << 8;   // (j*1024 + idx)*256
        float vj = sv[j];
        s1 = fmaf(vj, sW1[off + t], s1);
        y1 = fmaf(vj, yW1[off + t], y1);
    }
    s1 = fmaxf(s1, 0.f);
    y1 = fmaxf(y1, 0.f);
    g_S1[((size_t)row << 8) + t] = s1;
    float c = y1 * yW2[t];
    __shared__ float rs[8];
#pragma unroll
    for (int o = 16; o; o >>= 1) c += __shfl_xor_sync(0xffffffffu, c, o);
    if ((t & 31) == 0) rs[t >> 5] = c;
    __syncthreads();
    if (t == 0) {
        float tt = 0.f;
#pragma unroll
        for (int j = 0; j < 8; j++) tt += rs[j];
        out_syn[row] = tanhf(tt + yb2[0]);
    }
}

// =====================================================================
// K6: S2 = relu(S1[12800,256] @ sW2[256,128] + sb2); score = sigmoid(S2.sW3 + sb3)
// grid 100 blocks, 128 rows x 128 cols per block.
// =====================================================================
__global__ __launch_bounds__(256) void k_score(const float* __restrict__ W,
                                               const float* __restrict__ b2,
                                               const float* __restrict__ w3,
                                               const float* __restrict__ b3,
                                               float* __restrict__ out_scores)
{
    const int row0 = blockIdx.x << 7;
    __shared__ __align__(16) float As[32][128];
    __shared__ __align__(16) float Bs[32][128];
    __shared__ float red[128][17];
    const int t = threadIdx.x;
    const int tx = t & 15, ty = t >> 4;

    unsigned long long acc[8][4];
#pragma unroll
    for (int r = 0; r < 8; r++)
#pragma unroll
        for (int c = 0; c < 4; c++) acc[r][c] = 0ULL;

    for (int kk = 0; kk < 256; kk += 32) {
#pragma unroll
        for (int i = 0; i < 4; i++) {
            int idx = t + (i << 8);
            int b = idx >> 3, k4 = idx & 7;
            float4 v = *(const float4*)(g_S1 + (size_t)(row0 + b) * 256 + kk + (k4 << 2));
            int s = k4 << 2;
            int bc = b ^ s;
            As[s + 0][bc] = v.x;
            As[s + 1][bc] = v.y;
            As[s + 2][bc] = v.z;
            As[s + 3][bc] = v.w;
        }
#pragma unroll
        for (int i = 0; i < 4; i++) {
            int idx = t + (i << 8);
            int k = idx >> 5, n4 = idx & 31;
            *(float4*)&Bs[k][n4 << 2] = *(const float4*)(W + (kk + k) * 128 + (n4 << 2));
        }
        __syncthreads();
#pragma unroll
        for (int k = 0; k < 32; k++) {
            const int s = k & ~3;
            const float4 a0 = *(const float4*)&As[k][(ty << 3) ^ s];
            const float4 a1 = *(const float4*)&As[k][((ty << 3) + 4) ^ s];
            const ulonglong2 b01 = *(const ulonglong2*)&Bs[k][tx << 3];
            const ulonglong2 b23 = *(const ulonglong2*)&Bs[k][(tx << 3) + 4];
            float av[8] = {a0.x, a0.y, a0.z, a0.w, a1.x, a1.y, a1.z, a1.w};
#pragma unroll
            for (int r = 0; r < 8; r++) {
                unsigned long long aa;
                PACK2(aa, av[r]);
                FMA2(acc[r][0], aa, b01.x, acc[r][0]);
                FMA2(acc[r][1], aa, b01.y, acc[r][1]);
                FMA2(acc[r][2], aa, b23.x, acc[r][2]);
                FMA2(acc[r][3], aa, b23.y, acc[r][3]);
            }
        }
        __syncthreads();
    }

    float w3v[8], b2v[8];
#pragma unroll
    for (int c = 0; c < 8; c++) {
        w3v[c] = w3[(tx << 3) + c];
        b2v[c] = b2[(tx << 3) + c];
    }
#pragma unroll
    for (int r = 0; r < 8; r++) {
        float part = 0.f;
#pragma unroll
        for (int c = 0; c < 4; c++) {
            unsigned long long u = acc[r][c];
            float lo = __uint_as_float((unsigned)u);
            float hi = __uint_as_float((unsigned)(u >> 32));
            part += fmaxf(lo + b2v[2 * c], 0.f) * w3v[2 * c]
                  + fmaxf(hi + b2v[2 * c + 1], 0.f) * w3v[2 * c + 1];
        }
        red[(ty << 3) + r][tx] = part;
    }
    __syncthreads();
    if (t < 128) {
        float s = b3[0];
#pragma unroll
        for (int c = 0; c < 16; c++) s += red[t][c];
        out_scores[row0 + t] = 1.0f / (1.0f + __expf(-s));
    }
}

// =====================================================================
extern "C" void kernel_launch(void* const* d_in, const int* in_sizes, int n_in,
                              void* d_out, int out_size)
{
    (void)in_sizes; (void)n_in; (void)out_size;
    const float* x    = (const float*)d_in[0];
    const float* gum  = (const float*)d_in[1];
    const float* gW1  = (const float*)d_in[2];
    const float* gb1  = (const float*)d_in[3];
    const float* ln1s = (const float*)d_in[4];
    const float* ln1b = (const float*)d_in[5];
    const float* gW2  = (const float*)d_in[6];
    const float* gb2  = (const float*)d_in[7];
    const float* ln2s = (const float*)d_in[8];
    const float* ln2b = (const float*)d_in[9];
    const float* gW3  = (const float*)d_in[10];
    const float* gb3  = (const float*)d_in[11];
    const float* sW1  = (const float*)d_in[12];
    const float* sb1  = (const float*)d_in[13];
    const float* sW2  = (const float*)d_in[14];
    const float* sb2  = (const float*)d_in[15];
    const float* sW3  = (const float*)d_in[16];
    const float* sb3  = (const float*)d_in[17];
    const float* yW1  = (const float*)d_in[18];
    const float* yb1  = (const float*)d_in[19];
    const float* yW2  = (const float*)d_in[20];
    const float* yb2  = (const float*)d_in[21];

    float* out        = (float*)d_out;
    float* out_probs  = out;                       // [128,100,1024]
    float* out_scores = out + 13107200;            // [128,100]
    float* out_syn    = out + 13107200 + 12800;    // [128,100]
    float* out_logits = out + 13132800;            // [128,100,1024]

    k_gemm1<<<dim3(32, 2), 256>>>(x, gW1, gb1);
    k_ln1<<<128, 512>>>(ln1s, ln1b);
    k_gemm2<<<32, 256>>>(gW2, gb2);
    k_ln2<<<128, 256>>>(ln2s, ln2b);
    k_gemm3<<<dim3(8, 100), 256>>>(gW3, gb3, out_logits);
    k_softmax_top5<<<12800, 256>>>(out_logits, gum, out_probs);
    k_gather<<<12800, 256>>>(x, sW1, sb1, yW1, yb1, yW2, yb2, out_syn);
    k_score<<<100, 256>>>(sW2, sb2, sW3, sb3, out_scores);
}

// round 11
// speedup vs baseline: 1.1753x; 1.1753x over previous
#include <cuda_runtime.h>
#include <math.h>

#define Bn 128
#define Dn 1024
#define Hn 256
#define Mn 100
#define Kn 5
#define MD 102400   // M*D

// ---------------- scratch (device globals; no runtime alloc) ----------------
__device__ float g_h1[Bn * 512];
__device__ float g_t2[Bn * 256];
__device__ float g_h2[Bn * 256];
__device__ float g_S1[12800 * 256];

// ---------------- packed f32x2 helpers ----------------
#define FMA2(d, a, b, c) \
    asm("fma.rn.f32x2 %0, %1, %2, %3;" : "=l"(d) : "l"(a), "l"(b), "l"(c))
#define PACK2(d, x) \
    asm("mov.b64 %0, {%1, %1};" : "=l"(d) : "r"(__float_as_uint(x)))

static __device__ __forceinline__ unsigned long long umax64(unsigned long long a,
                                                            unsigned long long b)
{ return a > b ? a : b; }

// =====================================================================
// K1: h1 = relu(LN(x @ gW1 + gb1))   [fused GEMM + LN1]
// grid 32, block 512.  4 batch rows per block, all 512 cols.
// GEMM accumulation: k-ascending FFMA chain (bit-identical to prior rounds).
// LN reduction replicates the original ln_relu_body order exactly
// (per-warp butterfly over elems [32w,32w+32), then 16 partials in order).
// =====================================================================
__global__ __launch_bounds__(512) void k_gemm1ln1(const float* __restrict__ x,
                                                  const float* __restrict__ W,
                                                  const float* __restrict__ bias,
                                                  const float* __restrict__ sc,
                                                  const float* __restrict__ bi)
{
    const int b0 = blockIdx.x << 2;
    const int j  = threadIdx.x;                // 0..511
    __shared__ __align__(16) float xs[4][1024];
#pragma unroll
    for (int i = 0; i < 2; i++) {
        int idx = j + (i << 9);                // 0..1023 float4 slots
        int r = idx >> 8, k4 = idx & 255;
        *(float4*)&xs[r][k4 << 2] = *(const float4*)(x + (b0 + r) * 1024 + (k4 << 2));
    }
    __syncthreads();
    float acc0 = 0.f, acc1 = 0.f, acc2 = 0.f, acc3 = 0.f;
#pragma unroll 8
    for (int k = 0; k < 1024; k++) {
        float w = W[k * 512 + j];
        acc0 = fmaf(xs[0][k], w, acc0);
        acc1 = fmaf(xs[1][k], w, acc1);
        acc2 = fmaf(xs[2][k], w, acc2);
        acc3 = fmaf(xs[3][k], w, acc3);
    }
    float bb = bias[j];
    float v0 = acc0 + bb, v1 = acc1 + bb, v2 = acc2 + bb, v3 = acc3 + bb;

    // ---- LN over 512 cols for 4 rows, bit-exact vs original ln kernel ----
    __shared__ float sr[4][16];
    float s0 = v0, s1 = v1, s2 = v2, s3 = v3;
#pragma unroll
    for (int o = 16; o; o >>= 1) {
        s0 += __shfl_xor_sync(0xffffffffu, s0, o);
        s1 += __shfl_xor_sync(0xffffffffu, s1, o);
        s2 += __shfl_xor_sync(0xffffffffu, s2, o);
        s3 += __shfl_xor_sync(0xffffffffu, s3, o);
    }
    if ((j & 31) == 0) {
        int w = j >> 5;
        sr[0][w] = s0; sr[1][w] = s1; sr[2][w] = s2; sr[3][w] = s3;
    }
    __syncthreads();
    float mu0 = 0.f, mu1 = 0.f, mu2 = 0.f, mu3 = 0.f;
#pragma unroll
    for (int w = 0; w < 16; w++) {
        mu0 += sr[0][w]; mu1 += sr[1][w]; mu2 += sr[2][w]; mu3 += sr[3][w];
    }
    mu0 /= 512.0f; mu1 /= 512.0f; mu2 /= 512.0f; mu3 /= 512.0f;
    float d0 = v0 - mu0, d1 = v1 - mu1, d2 = v2 - mu2, d3 = v3 - mu3;
    __syncthreads();
    float q0 = d0 * d0, q1 = d1 * d1, q2 = d2 * d2, q3 = d3 * d3;
#pragma unroll
    for (int o = 16; o; o >>= 1) {
        q0 += __shfl_xor_sync(0xffffffffu, q0, o);
        q1 += __shfl_xor_sync(0xffffffffu, q1, o);
        q2 += __shfl_xor_sync(0xffffffffu, q2, o);
        q3 += __shfl_xor_sync(0xffffffffu, q3, o);
    }
    if ((j & 31) == 0) {
        int w = j >> 5;
        sr[0][w] = q0; sr[1][w] = q1; sr[2][w] = q2; sr[3][w] = q3;
    }
    __syncthreads();
    float t0 = 0.f, t1 = 0.f, t2 = 0.f, t3 = 0.f;
#pragma unroll
    for (int w = 0; w < 16; w++) {
        t0 += sr[0][w]; t1 += sr[1][w]; t2 += sr[2][w]; t3 += sr[3][w];
    }
    float scv = sc[j], biv = bi[j];
    float h0 = d0 * rsqrtf(t0 / 512.0f + 1e-5f) * scv + biv;
    float h1v = d1 * rsqrtf(t1 / 512.0f + 1e-5f) * scv + biv;
    float h2v = d2 * rsqrtf(t2 / 512.0f + 1e-5f) * scv + biv;
    float h3v = d3 * rsqrtf(t3 / 512.0f + 1e-5f) * scv + biv;
    g_h1[(b0 + 0) * 512 + j] = fmaxf(h0, 0.f);
    g_h1[(b0 + 1) * 512 + j] = fmaxf(h1v, 0.f);
    g_h1[(b0 + 2) * 512 + j] = fmaxf(h2v, 0.f);
    g_h1[(b0 + 3) * 512 + j] = fmaxf(h3v, 0.f);
}

// =====================================================================
// K2: t2 = h1[128,512] @ gW2[512,256] + gb2   grid 32, block 256  (unchanged)
// =====================================================================
__global__ __launch_bounds__(256) void k_gemm2(const float* __restrict__ W,
                                               const float* __restrict__ bias)
{
    const int b0 = blockIdx.x << 2;
    const int j  = threadIdx.x;
    __shared__ __align__(16) float xs[4][512];
#pragma unroll
    for (int i = 0; i < 2; i++) {
        int idx = threadIdx.x + (i << 8);          // 0..511 float4 slots
        int r = idx >> 7, k4 = idx & 127;
        *(float4*)&xs[r][k4 << 2] = *(const float4*)(g_h1 + (b0 + r) * 512 + (k4 << 2));
    }
    __syncthreads();
    float acc0 = 0.f, acc1 = 0.f, acc2 = 0.f, acc3 = 0.f;
#pragma unroll 8
    for (int k = 0; k < 512; k++) {
        float w = W[k * 256 + j];
        acc0 = fmaf(xs[0][k], w, acc0);
        acc1 = fmaf(xs[1][k], w, acc1);
        acc2 = fmaf(xs[2][k], w, acc2);
        acc3 = fmaf(xs[3][k], w, acc3);
    }
    float bb = bias[j];
    g_t2[(b0 + 0) * 256 + j] = acc0 + bb;
    g_t2[(b0 + 1) * 256 + j] = acc1 + bb;
    g_t2[(b0 + 2) * 256 + j] = acc2 + bb;
    g_t2[(b0 + 3) * 256 + j] = acc3 + bb;
}

// ---------------- LN2 + ReLU (block per row, blockDim = 256) -- unchanged ----
__global__ void k_ln2(const float* __restrict__ sc, const float* __restrict__ bi)
{
    const int n = blockDim.x;
    const int b = blockIdx.x, t = threadIdx.x;
    float v = g_t2[b * n + t];
    __shared__ float sr[16];
    float s = v;
#pragma unroll
    for (int o = 16; o; o >>= 1) s += __shfl_xor_sync(0xffffffffu, s, o);
    if ((t & 31) == 0) sr[t >> 5] = s;
    __syncthreads();
    const int nw = n >> 5;
    float tot = 0.f;
    for (int jj = 0; jj < nw; jj++) tot += sr[jj];
    float mu = tot / (float)n;
    float d = v - mu;
    __syncthreads();
    float q = d * d;
#pragma unroll
    for (int o = 16; o; o >>= 1) q += __shfl_xor_sync(0xffffffffu, q, o);
    if ((t & 31) == 0) sr[t >> 5] = q;
    __syncthreads();
    float tv = 0.f;
    for (int jj = 0; jj < nw; jj++) tv += sr[jj];
    float var = tv / (float)n;
    float hv = d * rsqrtf(var + 1e-5f) * sc[t] + bi[t];
    g_h2[b * n + t] = fmaxf(hv, 0.f);
}

// =====================================================================
// K3: logits = h2[128,256] @ gW3[256,102400] + gb3
// grid (8, 100), 256 threads, 8x8 micro-tile, f32x2 FMAs, XOR-swizzled A.
// NOW with register-prefetch pipeline: next K-tile's global loads are
// issued before the compute phase. Accumulation order unchanged (bit-exact).
// =====================================================================
__global__ __launch_bounds__(256) void k_gemm3(const float* __restrict__ W,
                                               const float* __restrict__ bias,
                                               float* __restrict__ out)
{
    const int m    = blockIdx.y;
    const int nb   = blockIdx.x << 7;
    const int col0 = m * 1024 + nb;
    __shared__ __align__(16) float As[32][128];   // As[k][b ^ (k&~3)]
    __shared__ __align__(16) float Bs[32][128];   // Bs[k][n]
    const int t  = threadIdx.x;
    const int tx = t & 15, ty = t >> 4;

    // frag coordinates (constant per thread)
    const int a_k4 = t & 7;        // float4 slot within 32-k
    const int a_b0 = t >> 3;       // base row (i-th frag: + 32*i)
    const int b_n4 = t & 31;       // float4 slot within 128-n
    const int b_k0 = t >> 5;       // base k (i-th frag: + 8*i)

    float4 ra[4], rb[4];
#pragma unroll
    for (int i = 0; i < 4; i++)
        ra[i] = *(const float4*)(g_h2 + (a_b0 + (i << 5)) * 256 + (a_k4 << 2));
#pragma unroll
    for (int i = 0; i < 4; i++)
        rb[i] = *(const float4*)(W + (size_t)(b_k0 + (i << 3)) * MD + col0 + (b_n4 << 2));

    unsigned long long acc[8][4];
#pragma unroll
    for (int r = 0; r < 8; r++)
#pragma unroll
        for (int c = 0; c < 4; c++) acc[r][c] = 0ULL;

    for (int kk = 0; kk < 256; kk += 32) {
        // commit prefetched frags to smem
        {
            const int s = a_k4 << 2;
#pragma unroll
            for (int i = 0; i < 4; i++) {
                int bc = (a_b0 + (i << 5)) ^ s;
                As[s + 0][bc] = ra[i].x;
                As[s + 1][bc] = ra[i].y;
                As[s + 2][bc] = ra[i].z;
                As[s + 3][bc] = ra[i].w;
            }
#pragma unroll
            for (int i = 0; i < 4; i++)
                *(float4*)&Bs[b_k0 + (i << 3)][b_n4 << 2] = rb[i];
        }
        __syncthreads();
        // prefetch next tile while computing this one
        if (kk < 224) {
            const int kn = kk + 32;
#pragma unroll
            for (int i = 0; i < 4; i++)
                ra[i] = *(const float4*)(g_h2 + (a_b0 + (i << 5)) * 256 + kn + (a_k4 << 2));
#pragma unroll
            for (int i = 0; i < 4; i++)
                rb[i] = *(const float4*)(W + (size_t)(kn + b_k0 + (i << 3)) * MD + col0 + (b_n4 << 2));
        }
#pragma unroll
        for (int k = 0; k < 32; k++) {
            const int s = k & ~3;
            const float4 a0 = *(const float4*)&As[k][(ty << 3) ^ s];
            const float4 a1 = *(const float4*)&As[k][((ty << 3) + 4) ^ s];
            const ulonglong2 b01 = *(const ulonglong2*)&Bs[k][tx << 3];
            const ulonglong2 b23 = *(const ulonglong2*)&Bs[k][(tx << 3) + 4];
            float av[8] = {a0.x, a0.y, a0.z, a0.w, a1.x, a1.y, a1.z, a1.w};
#pragma unroll
            for (int r = 0; r < 8; r++) {
                unsigned long long aa;
                PACK2(aa, av[r]);
                FMA2(acc[r][0], aa, b01.x, acc[r][0]);
                FMA2(acc[r][1], aa, b01.y, acc[r][1]);
                FMA2(acc[r][2], aa, b23.x, acc[r][2]);
                FMA2(acc[r][3], aa, b23.y, acc[r][3]);
            }
        }
        __syncthreads();
    }

    float bias0[8];
    const float* bp = bias + col0 + (tx << 3);
#pragma unroll
    for (int c = 0; c < 8; c++) bias0[c] = bp[c];
#pragma unroll
    for (int r = 0; r < 8; r++) {
        int b = (ty << 3) + r;
        float o[8];
#pragma unroll
        for (int c = 0; c < 4; c++) {
            unsigned long long u = acc[r][c];
            o[2 * c]     = __uint_as_float((unsigned)u) + bias0[2 * c];
            o[2 * c + 1] = __uint_as_float((unsigned)(u >> 32)) + bias0[2 * c + 1];
        }
        float4* dst = (float4*)(out + (size_t)b * MD + col0 + (tx << 3));
        dst[0] = make_float4(o[0], o[1], o[2], o[3]);
        dst[1] = make_float4(o[4], o[5], o[6], o[7]);
    }
}

// =====================================================================
// K4 (fused): per (b,m) row:
//   probs = softmax(2*(logits+gumbel))           -> out
//   top-5 on RAW z via packed u64 keys (z desc, idx asc tie-break)
//   s1 = relu(gather sW1), y1 = relu(gather yW1) -> g_S1, synergy -> out
// grid 12800, block 256.
// =====================================================================
__global__ __launch_bounds__(256) void k_fused(const float* __restrict__ logits,
                                               const float* __restrict__ gum,
                                               const float* __restrict__ x,
                                               const float* __restrict__ sW1,
                                               const float* __restrict__ sb1,
                                               const float* __restrict__ yW1,
                                               const float* __restrict__ yb1,
                                               const float* __restrict__ yW2,
                                               const float* __restrict__ yb2,
                                               float* __restrict__ probs,
                                               float* __restrict__ out_syn)
{
    const int row = blockIdx.x;
    const int t = threadIdx.x;
    const float* lp = logits + (size_t)row * 1024;
    const float* gp = gum + (size_t)row * 1024;
    float zv[4];
#pragma unroll
    for (int i = 0; i < 4; i++) {
        int d = t + (i << 8);
        zv[i] = lp[d] + gp[d];                 // raw z
    }
    __shared__ float sred[8];
    float mx = fmaxf(fmaxf(zv[0], zv[1]), fmaxf(zv[2], zv[3]));
#pragma unroll
    for (int o = 16; o; o >>= 1) mx = fmaxf(mx, __shfl_xor_sync(0xffffffffu, mx, o));
    if ((t & 31) == 0) sred[t >> 5] = mx;
    __syncthreads();
    float rmax = sred[0];
#pragma unroll
    for (int jj = 1; jj < 8; jj++) rmax = fmaxf(rmax, sred[jj]);
    float ev[4], lsum = 0.f;
#pragma unroll
    for (int i = 0; i < 4; i++) { ev[i] = __expf(2.0f * (zv[i] - rmax)); lsum += ev[i]; }
    __syncthreads();
#pragma unroll
    for (int o = 16; o; o >>= 1) lsum += __shfl_xor_sync(0xffffffffu, lsum, o);
    if ((t & 31) == 0) sred[t >> 5] = lsum;
    __syncthreads();
    float tot = 0.f;
#pragma unroll
    for (int jj = 0; jj < 8; jj++) tot += sred[jj];
    float inv = 1.0f / tot;
#pragma unroll
    for (int i = 0; i < 4; i++)
        probs[(size_t)row * 1024 + t + (i << 8)] = ev[i] * inv;

    // ---- top-5 via packed u64 keys: (ordered(z) << 32) | (0xFFFFFFFF - idx) ----
    unsigned long long key[4];
#pragma unroll
    for (int i = 0; i < 4; i++) {
        unsigned sb = __float_as_uint(zv[i]);
        unsigned ord = (sb & 0x80000000u) ? ~sb : (sb | 0x80000000u);
        key[i] = ((unsigned long long)ord << 32) | (unsigned)(0xFFFFFFFFu - (t + (i << 8)));
    }
    __shared__ unsigned long long skey[8];
    __shared__ unsigned long long s_win;
    __shared__ int si[5];
    __shared__ float sv[5];
#pragma unroll
    for (int r5 = 0; r5 < 5; r5++) {
        unsigned long long mkey = umax64(umax64(key[0], key[1]), umax64(key[2], key[3]));
#pragma unroll
        for (int o = 16; o; o >>= 1)
            mkey = umax64(mkey, __shfl_xor_sync(0xffffffffu, mkey, o));
        if ((t & 31) == 0) skey[t >> 5] = mkey;
        __syncthreads();
        if (t < 32) {
            unsigned long long v = (t < 8) ? skey[t] : 0ULL;
            v = umax64(v, __shfl_xor_sync(0xffffffffu, v, 4));
            v = umax64(v, __shfl_xor_sync(0xffffffffu, v, 2));
            v = umax64(v, __shfl_xor_sync(0xffffffffu, v, 1));
            if (t == 0) {
                s_win = v;
                si[r5] = (int)(~(unsigned)v);
            }
        }
        __syncthreads();
        unsigned long long w = s_win;
#pragma unroll
        for (int i = 0; i < 4; i++)
            if (key[i] == w) key[i] = 0ULL;
    }
    __syncthreads();
    if (t < 5) sv[t] = x[(row / 100) * 1024 + si[t]];
    __syncthreads();

    // ---- gather GEMV + synergy (same math/order as previous k_gather) ----
    float s1 = sb1[t], y1 = yb1[t];
#pragma unroll
    for (int jj = 0; jj < 5; jj++) {
        int off = ((jj << 10) + si[jj]) << 8;   // (j*1024 + idx)*256
        float vj = sv[jj];
        s1 = fmaf(vj, sW1[off + t], s1);
        y1 = fmaf(vj, yW1[off + t], y1);
    }
    s1 = fmaxf(s1, 0.f);
    y1 = fmaxf(y1, 0.f);
    g_S1[((size_t)row << 8) + t] = s1;
    float c = y1 * yW2[t];
    __shared__ float rs[8];
#pragma unroll
    for (int o = 16; o; o >>= 1) c += __shfl_xor_sync(0xffffffffu, c, o);
    if ((t & 31) == 0) rs[t >> 5] = c;
    __syncthreads();
    if (t == 0) {
        float tt = 0.f;
#pragma unroll
        for (int jj = 0; jj < 8; jj++) tt += rs[jj];
        out_syn[row] = tanhf(tt + yb2[0]);
    }
}

// =====================================================================
// K6: S2 = relu(S1 @ sW2 + sb2); score = sigmoid(S2 . sW3 + sb3)
// grid 400 (32 rows each), block 256: tx = 4 cols x32, ty = 4 rows x8.
// =====================================================================
__global__ __launch_bounds__(256) void k_score(const float* __restrict__ W,
                                               const float* __restrict__ b2,
                                               const float* __restrict__ w3,
                                               const float* __restrict__ b3,
                                               float* __restrict__ out_scores)
{
    const int row0 = blockIdx.x << 5;          // 32 rows
    __shared__ float As[32][33];               // [row][k] padded
    __shared__ __align__(16) float Bs[32][128];
    __shared__ float red[32][33];
    const int t  = threadIdx.x;
    const int tx = t & 31;                     // 4 cols each
    const int ty = t >> 5;                     // 4 rows each

    unsigned long long acc[4][2];
#pragma unroll
    for (int r = 0; r < 4; r++) { acc[r][0] = 0ULL; acc[r][1] = 0ULL; }

    for (int kk = 0; kk < 256; kk += 32) {
        {   // A: 32 rows x 32 k  (one float4 per thread)
            int r = t >> 3, k4 = t & 7;
            float4 v = *(const float4*)(g_S1 + (size_t)(row0 + r) * 256 + kk + (k4 << 2));
            As[r][(k4 << 2) + 0] = v.x;
            As[r][(k4 << 2) + 1] = v.y;
            As[r][(k4 << 2) + 2] = v.z;
            As[r][(k4 << 2) + 3] = v.w;
        }
#pragma unroll
        for (int i = 0; i < 4; i++) {          // B: 32 k x 128 n
            int idx = t + (i << 8);
            int k = idx >> 5, n4 = idx & 31;
            *(float4*)&Bs[k][n4 << 2] = *(const float4*)(W + (kk + k) * 128 + (n4 << 2));
        }
        __syncthreads();
#pragma unroll
        for (int k = 0; k < 32; k++) {
            const ulonglong2 b01 = *(const ulonglong2*)&Bs[k][tx << 2];
#pragma unroll
            for (int r = 0; r < 4; r++) {
                unsigned long long aa;
                PACK2(aa, As[(ty << 2) + r][k]);
                FMA2(acc[r][0], aa, b01.x, acc[r][0]);
                FMA2(acc[r][1], aa, b01.y, acc[r][1]);
            }
        }
        __syncthreads();
    }

    float b2v[4], w3v[4];
#pragma unroll
    for (int c = 0; c < 4; c++) {
        b2v[c] = b2[(tx << 2) + c];
        w3v[c] = w3[(tx << 2) + c];
    }
#pragma unroll
    for (int r = 0; r < 4; r++) {
        float part = 0.f;
        {
            unsigned long long u = acc[r][0];
            float lo = __uint_as_float((unsigned)u);
            float hi = __uint_as_float((unsigned)(u >> 32));
            part += fmaxf(lo + b2v[0], 0.f) * w3v[0] + fmaxf(hi + b2v[1], 0.f) * w3v[1];
        }
        {
            unsigned long long u = acc[r][1];
            float lo = __uint_as_float((unsigned)u);
            float hi = __uint_as_float((unsigned)(u >> 32));
            part += fmaxf(lo + b2v[2], 0.f) * w3v[2] + fmaxf(hi + b2v[3], 0.f) * w3v[3];
        }
        red[(ty << 2) + r][tx] = part;
    }
    __syncthreads();
    if (t < 32) {
        float s = b3[0];
#pragma unroll
        for (int c = 0; c < 32; c++) s += red[t][c];
        out_scores[row0 + t] = 1.0f / (1.0f + __expf(-s));
    }
}

// =====================================================================
extern "C" void kernel_launch(void* const* d_in, const int* in_sizes, int n_in,
                              void* d_out, int out_size)
{
    (void)in_sizes; (void)n_in; (void)out_size;
    const float* x    = (const float*)d_in[0];
    const float* gum  = (const float*)d_in[1];
    const float* gW1  = (const float*)d_in[2];
    const float* gb1  = (const float*)d_in[3];
    const float* ln1s = (const float*)d_in[4];
    const float* ln1b = (const float*)d_in[5];
    const float* gW2  = (const float*)d_in[6];
    const float* gb2  = (const float*)d_in[7];
    const float* ln2s = (const float*)d_in[8];
    const float* ln2b = (const float*)d_in[9];
    const float* gW3  = (const float*)d_in[10];
    const float* gb3  = (const float*)d_in[11];
    const float* sW1  = (const float*)d_in[12];
    const float* sb1  = (const float*)d_in[13];
    const float* sW2  = (const float*)d_in[14];
    const float* sb2  = (const float*)d_in[15];
    const float* sW3  = (const float*)d_in[16];
    const float* sb3  = (const float*)d_in[17];
    const float* yW1  = (const float*)d_in[18];
    const float* yb1  = (const float*)d_in[19];
    const float* yW2  = (const float*)d_in[20];
    const float* yb2  = (const float*)d_in[21];

    float* out        = (float*)d_out;
    float* out_probs  = out;                       // [128,100,1024]
    float* out_scores = out + 13107200;            // [128,100]
    float* out_syn    = out + 13107200 + 12800;    // [128,100]
    float* out_logits = out + 13132800;            // [128,100,1024]

    k_gemm1ln1<<<32, 512>>>(x, gW1, gb1, ln1s, ln1b);          // 1
    k_gemm2<<<32, 256>>>(gW2, gb2);                             // 2
    k_ln2<<<128, 256>>>(ln2s, ln2b);                            // 3
    k_gemm3<<<dim3(8, 100), 256>>>(gW3, gb3, out_logits);       // 4 <- ncu slot
    k_fused<<<12800, 256>>>(out_logits, gum, x, sW1, sb1,
                            yW1, yb1, yW2, yb2, out_probs, out_syn);  // 5
    k_score<<<400, 256>>>(sW2, sb2, sW3, sb3, out_scores);      // 6
}

// round 15
// speedup vs baseline: 1.4475x; 1.2316x over previous
#include <cuda_runtime.h>
#include <math.h>

#define Bn 128
#define Dn 1024
#define Hn 256
#define Mn 100
#define Kn 5
#define MD 102400   // M*D

// ---------------- scratch (device globals; no runtime alloc) ----------------
__device__ float g_h1[Bn * 512];
__device__ float g_t2[Bn * 256];
__device__ float g_h2[Bn * 256];
__device__ float g_S1[12800 * 256];

// ---------------- packed f32x2 helpers ----------------
#define FMA2(d, a, b, c) \
    asm("fma.rn.f32x2 %0, %1, %2, %3;" : "=l"(d) : "l"(a), "l"(b), "l"(c))
#define PACK2(d, x) \
    asm("mov.b64 %0, {%1, %1};" : "=l"(d) : "r"(__float_as_uint(x)))

// ---------------- cp.async helpers ----------------
#define CPASYNC16(dst_u32, src_ptr) \
    asm volatile("cp.async.cg.shared.global [%0], [%1], 16;" :: "r"(dst_u32), "l"(src_ptr))
#define CPCOMMIT() asm volatile("cp.async.commit_group;")
#define CPWAIT1()  asm volatile("cp.async.wait_group 1;")
#define CPWAIT0()  asm volatile("cp.async.wait_group 0;")

static __device__ __forceinline__ unsigned sptr(const void* p)
{ return (unsigned)__cvta_generic_to_shared(p); }

static __device__ __forceinline__ unsigned redux_max_u32(unsigned v)
{ unsigned r; asm("redux.sync.max.u32 %0, %1, 0xffffffff;" : "=r"(r) : "r"(v)); return r; }
static __device__ __forceinline__ unsigned redux_min_u32(unsigned v)
{ unsigned r; asm("redux.sync.min.u32 %0, %1, 0xffffffff;" : "=r"(r) : "r"(v)); return r; }

// =====================================================================
// K1: h1 = relu(LN(x @ gW1 + gb1))   [fused GEMM + LN1]  (unchanged)
// =====================================================================
__global__ __launch_bounds__(512) void k_gemm1ln1(const float* __restrict__ x,
                                                  const float* __restrict__ W,
                                                  const float* __restrict__ bias,
                                                  const float* __restrict__ sc,
                                                  const float* __restrict__ bi)
{
    const int b0 = blockIdx.x << 2;
    const int j  = threadIdx.x;                // 0..511
    __shared__ __align__(16) float xs[4][1024];
#pragma unroll
    for (int i = 0; i < 2; i++) {
        int idx = j + (i << 9);                // 0..1023 float4 slots
        int r = idx >> 8, k4 = idx & 255;
        *(float4*)&xs[r][k4 << 2] = *(const float4*)(x + (b0 + r) * 1024 + (k4 << 2));
    }
    __syncthreads();
    float acc0 = 0.f, acc1 = 0.f, acc2 = 0.f, acc3 = 0.f;
#pragma unroll 8
    for (int k = 0; k < 1024; k++) {
        float w = W[k * 512 + j];
        acc0 = fmaf(xs[0][k], w, acc0);
        acc1 = fmaf(xs[1][k], w, acc1);
        acc2 = fmaf(xs[2][k], w, acc2);
        acc3 = fmaf(xs[3][k], w, acc3);
    }
    float bb = bias[j];
    float v0 = acc0 + bb, v1 = acc1 + bb, v2 = acc2 + bb, v3 = acc3 + bb;

    __shared__ float sr[4][16];
    float s0 = v0, s1 = v1, s2 = v2, s3 = v3;
#pragma unroll
    for (int o = 16; o; o >>= 1) {
        s0 += __shfl_xor_sync(0xffffffffu, s0, o);
        s1 += __shfl_xor_sync(0xffffffffu, s1, o);
        s2 += __shfl_xor_sync(0xffffffffu, s2, o);
        s3 += __shfl_xor_sync(0xffffffffu, s3, o);
    }
    if ((j & 31) == 0) {
        int w = j >> 5;
        sr[0][w] = s0; sr[1][w] = s1; sr[2][w] = s2; sr[3][w] = s3;
    }
    __syncthreads();
    float mu0 = 0.f, mu1 = 0.f, mu2 = 0.f, mu3 = 0.f;
#pragma unroll
    for (int w = 0; w < 16; w++) {
        mu0 += sr[0][w]; mu1 += sr[1][w]; mu2 += sr[2][w]; mu3 += sr[3][w];
    }
    mu0 /= 512.0f; mu1 /= 512.0f; mu2 /= 512.0f; mu3 /= 512.0f;
    float d0 = v0 - mu0, d1 = v1 - mu1, d2 = v2 - mu2, d3 = v3 - mu3;
    __syncthreads();
    float q0 = d0 * d0, q1 = d1 * d1, q2 = d2 * d2, q3 = d3 * d3;
#pragma unroll
    for (int o = 16; o; o >>= 1) {
        q0 += __shfl_xor_sync(0xffffffffu, q0, o);
        q1 += __shfl_xor_sync(0xffffffffu, q1, o);
        q2 += __shfl_xor_sync(0xffffffffu, q2, o);
        q3 += __shfl_xor_sync(0xffffffffu, q3, o);
    }
    if ((j & 31) == 0) {
        int w = j >> 5;
        sr[0][w] = q0; sr[1][w] = q1; sr[2][w] = q2; sr[3][w] = q3;
    }
    __syncthreads();
    float t0 = 0.f, t1 = 0.f, t2 = 0.f, t3 = 0.f;
#pragma unroll
    for (int w = 0; w < 16; w++) {
        t0 += sr[0][w]; t1 += sr[1][w]; t2 += sr[2][w]; t3 += sr[3][w];
    }
    float scv = sc[j], biv = bi[j];
    float h0 = d0 * rsqrtf(t0 / 512.0f + 1e-5f) * scv + biv;
    float h1v = d1 * rsqrtf(t1 / 512.0f + 1e-5f) * scv + biv;
    float h2v = d2 * rsqrtf(t2 / 512.0f + 1e-5f) * scv + biv;
    float h3v = d3 * rsqrtf(t3 / 512.0f + 1e-5f) * scv + biv;
    g_h1[(b0 + 0) * 512 + j] = fmaxf(h0, 0.f);
    g_h1[(b0 + 1) * 512 + j] = fmaxf(h1v, 0.f);
    g_h1[(b0 + 2) * 512 + j] = fmaxf(h2v, 0.f);
    g_h1[(b0 + 3) * 512 + j] = fmaxf(h3v, 0.f);
}

// =====================================================================
// K2: t2 = h1 @ gW2 + gb2   (unchanged)
// =====================================================================
__global__ __launch_bounds__(256) void k_gemm2(const float* __restrict__ W,
                                               const float* __restrict__ bias)
{
    const int b0 = blockIdx.x << 2;
    const int j  = threadIdx.x;
    __shared__ __align__(16) float xs[4][512];
#pragma unroll
    for (int i = 0; i < 2; i++) {
        int idx = threadIdx.x + (i << 8);
        int r = idx >> 7, k4 = idx & 127;
        *(float4*)&xs[r][k4 << 2] = *(const float4*)(g_h1 + (b0 + r) * 512 + (k4 << 2));
    }
    __syncthreads();
    float acc0 = 0.f, acc1 = 0.f, acc2 = 0.f, acc3 = 0.f;
#pragma unroll 8
    for (int k = 0; k < 512; k++) {
        float w = W[k * 256 + j];
        acc0 = fmaf(xs[0][k], w, acc0);
        acc1 = fmaf(xs[1][k], w, acc1);
        acc2 = fmaf(xs[2][k], w, acc2);
        acc3 = fmaf(xs[3][k], w, acc3);
    }
    float bb = bias[j];
    g_t2[(b0 + 0) * 256 + j] = acc0 + bb;
    g_t2[(b0 + 1) * 256 + j] = acc1 + bb;
    g_t2[(b0 + 2) * 256 + j] = acc2 + bb;
    g_t2[(b0 + 3) * 256 + j] = acc3 + bb;
}

// ---------------- LN2 + ReLU (unchanged) ----------------
__global__ void k_ln2(const float* __restrict__ sc, const float* __restrict__ bi)
{
    const int n = blockDim.x;
    const int b = blockIdx.x, t = threadIdx.x;
    float v = g_t2[b * n + t];
    __shared__ float sr[16];
    float s = v;
#pragma unroll
    for (int o = 16; o; o >>= 1) s += __shfl_xor_sync(0xffffffffu, s, o);
    if ((t & 31) == 0) sr[t >> 5] = s;
    __syncthreads();
    const int nw = n >> 5;
    float tot = 0.f;
    for (int jj = 0; jj < nw; jj++) tot += sr[jj];
    float mu = tot / (float)n;
    float d = v - mu;
    __syncthreads();
    float q = d * d;
#pragma unroll
    for (int o = 16; o; o >>= 1) q += __shfl_xor_sync(0xffffffffu, q, o);
    if ((t & 31) == 0) sr[t >> 5] = q;
    __syncthreads();
    float tv = 0.f;
    for (int jj = 0; jj < nw; jj++) tv += sr[jj];
    float var = tv / (float)n;
    float hv = d * rsqrtf(var + 1e-5f) * sc[t] + bi[t];
    g_h2[b * n + t] = fmaxf(hv, 0.f);
}

// =====================================================================
// K3: logits = h2[128,256] @ gW3[256,102400] + gb3
// grid 400, 256 threads. Block tile 128 rows x 256 cols, k-tile 16,
// double-buffered: B via cp.async (bypasses regs), A via LDG+swizzled STS.
// Per-thread micro-tile 16 rows x 8 cols (f32x2 accumulators).
// A-frag LDS are warp-broadcast (all lanes share ty); B-frag LDS are
// contiguous conflict-free. Accumulation per element is a single fp32
// FMA chain in ascending k -> logits bit-identical to prior rounds.
// =====================================================================
__global__ __launch_bounds__(256) void k_gemm3(const float* __restrict__ W,
                                               const float* __restrict__ bias,
                                               float* __restrict__ out)
{
    const int col0 = blockIdx.x << 8;          // 256 cols per block
    __shared__ __align__(16) float As[2][16][128];   // 2 x 8KB
    __shared__ __align__(16) float Bs[2][16][256];   // 2 x 16KB
    const int t  = threadIdx.x;
    const int tx = t & 31;                     // col group: cols 4tx, 4tx+128
    const int ty = t >> 5;                     // row group: rows 16ty..16ty+15

    // A load mapping: 128 rows x 4 float4-slots per tile; 2 per thread
    const int a_row0 = t >> 2;                 // idx = t     -> row
    const int a_row1 = (t + 256) >> 2;         // idx = t+256 -> row
    const int a_k4   = t & 3;                  // same for both (t & 3)
    const int a_s    = a_k4 << 2;

    // B cp.async mapping: 1024 16B-chunks per tile; 4 per thread
    // chunk = t + 256*i : k = chunk>>6, n4 = chunk&63
    unsigned bdst[4];
    const float* bsrc_base = W + col0;
#pragma unroll
    for (int i = 0; i < 4; i++) {
        int chunk = t + (i << 8);
        bdst[i] = sptr(&Bs[0][chunk >> 6][(chunk & 63) << 2]);
    }
    const unsigned bufstride = (unsigned)(16 * 256 * 4);   // bytes between Bs[0] and Bs[1]

    // prologue: B tile 0 -> Bs[0]
#pragma unroll
    for (int i = 0; i < 4; i++) {
        int chunk = t + (i << 8);
        CPASYNC16(bdst[i], bsrc_base + (size_t)(chunk >> 6) * MD + ((chunk & 63) << 2));
    }
    CPCOMMIT();
    // A tile 0 -> regs
    float4 ra0 = *(const float4*)(g_h2 + a_row0 * 256 + (a_k4 << 2));
    float4 ra1 = *(const float4*)(g_h2 + a_row1 * 256 + (a_k4 << 2));

    unsigned long long acc[16][4];
#pragma unroll
    for (int r = 0; r < 16; r++)
#pragma unroll
        for (int c = 0; c < 4; c++) acc[r][c] = 0ULL;

    for (int kt = 0; kt < 16; kt++) {
        const int buf = kt & 1;
        // commit A regs to smem (swizzled)
        As[buf][a_s + 0][a_row0 ^ a_s] = ra0.x;
        As[buf][a_s + 1][a_row0 ^ a_s] = ra0.y;
        As[buf][a_s + 2][a_row0 ^ a_s] = ra0.z;
        As[buf][a_s + 3][a_row0 ^ a_s] = ra0.w;
        As[buf][a_s + 0][a_row1 ^ a_s] = ra1.x;
        As[buf][a_s + 1][a_row1 ^ a_s] = ra1.y;
        As[buf][a_s + 2][a_row1 ^ a_s] = ra1.z;
        As[buf][a_s + 3][a_row1 ^ a_s] = ra1.w;
        if (kt < 15) {
            const int kn = (kt + 1) << 4;
            // next B tile -> other buffer
            const unsigned off = (buf ^ 1) ? bufstride : 0u;
#pragma unroll
            for (int i = 0; i < 4; i++) {
                int chunk = t + (i << 8);
                CPASYNC16(bdst[i] + off - (buf ? bufstride : 0u) * 0u,   // base bdst is buf0
                          bsrc_base + (size_t)(kn + (chunk >> 6)) * MD + ((chunk & 63) << 2));
            }
            CPCOMMIT();
            // next A tile -> regs
            ra0 = *(const float4*)(g_h2 + a_row0 * 256 + kn + (a_k4 << 2));
            ra1 = *(const float4*)(g_h2 + a_row1 * 256 + kn + (a_k4 << 2));
            CPWAIT1();
        } else {
            CPWAIT0();
        }
        __syncthreads();
#pragma unroll
        for (int k = 0; k < 16; k++) {
            const int s = k & ~3;
            const float4 a0 = *(const float4*)&As[buf][k][((ty << 4) + 0) ^ s];
            const float4 a1 = *(const float4*)&As[buf][k][((ty << 4) + 4) ^ s];
            const float4 a2 = *(const float4*)&As[buf][k][((ty << 4) + 8) ^ s];
            const float4 a3 = *(const float4*)&As[buf][k][((ty << 4) + 12) ^ s];
            const ulonglong2 b01 = *(const ulonglong2*)&Bs[buf][k][tx << 2];
            const ulonglong2 b23 = *(const ulonglong2*)&Bs[buf][k][(tx << 2) + 128];
            float av[16] = {a0.x, a0.y, a0.z, a0.w, a1.x, a1.y, a1.z, a1.w,
                            a2.x, a2.y, a2.z, a2.w, a3.x, a3.y, a3.z, a3.w};
#pragma unroll
            for (int r = 0; r < 16; r++) {
                unsigned long long aa;
                PACK2(aa, av[r]);
                FMA2(acc[r][0], aa, b01.x, acc[r][0]);
                FMA2(acc[r][1], aa, b01.y, acc[r][1]);
                FMA2(acc[r][2], aa, b23.x, acc[r][2]);
                FMA2(acc[r][3], aa, b23.y, acc[r][3]);
            }
        }
        __syncthreads();
    }

    // epilogue: bias + store. cols: c1 = col0+4tx (.. +3), c2 = c1+128
    const int c1 = col0 + (tx << 2);
    float bA[4], bB[4];
#pragma unroll
    for (int j = 0; j < 4; j++) { bA[j] = bias[c1 + j]; bB[j] = bias[c1 + 128 + j]; }
#pragma unroll
    for (int r = 0; r < 16; r++) {
        int b = (ty << 4) + r;
        float o1[4], o2[4];
#pragma unroll
        for (int c = 0; c < 2; c++) {
            unsigned long long u = acc[r][c];
            o1[2 * c]     = __uint_as_float((unsigned)u) + bA[2 * c];
            o1[2 * c + 1] = __uint_as_float((unsigned)(u >> 32)) + bA[2 * c + 1];
            unsigned long long v = acc[r][c + 2];
            o2[2 * c]     = __uint_as_float((unsigned)v) + bB[2 * c];
            o2[2 * c + 1] = __uint_as_float((unsigned)(v >> 32)) + bB[2 * c + 1];
        }
        *(float4*)(out + (size_t)b * MD + c1)       = make_float4(o1[0], o1[1], o1[2], o1[3]);
        *(float4*)(out + (size_t)b * MD + c1 + 128) = make_float4(o2[0], o2[1], o2[2], o2[3]);
    }
}

// =====================================================================
// K4 (fused): per (b,m) row:
//   probs = softmax(2*(logits+gumbel)) (float4 I/O)
//   top-5 on RAW z (exact): warp-local top-5 via redux.sync, then warp-0
//   merge of 40 candidates. Tie-break = smallest index (== lax.top_k).
//   gather GEMV s1/y1 + synergy. grid 12800, block 256.
// =====================================================================
__global__ __launch_bounds__(256) void k_fused(const float* __restrict__ logits,
                                               const float* __restrict__ gum,
                                               const float* __restrict__ x,
                                               const float* __restrict__ sW1,
                                               const float* __restrict__ sb1,
                                               const float* __restrict__ yW1,
                                               const float* __restrict__ yb1,
                                               const float* __restrict__ yW2,
                                               const float* __restrict__ yb2,
                                               float* __restrict__ probs,
                                               float* __restrict__ out_syn)
{
    const int row = blockIdx.x;
    const int t = threadIdx.x;
    const int lane = t & 31, warp = t >> 5;
    const float4 l4 = *((const float4*)(logits + (size_t)row * 1024) + t);
    const float4 g4 = *((const float4*)(gum + (size_t)row * 1024) + t);
    float zv[4] = {l4.x + g4.x, l4.y + g4.y, l4.z + g4.z, l4.w + g4.w};

    __shared__ float sred[8];
    // ---- max ----
    float mx = fmaxf(fmaxf(zv[0], zv[1]), fmaxf(zv[2], zv[3]));
#pragma unroll
    for (int o = 16; o; o >>= 1) mx = fmaxf(mx, __shfl_xor_sync(0xffffffffu, mx, o));
    if (lane == 0) sred[warp] = mx;
    __syncthreads();
    float rmax = sred[0];
#pragma unroll
    for (int jj = 1; jj < 8; jj++) rmax = fmaxf(rmax, sred[jj]);
    // ---- exp + sum ----
    float ev[4], lsum;
#pragma unroll
    for (int i = 0; i < 4; i++) ev[i] = __expf(2.0f * (zv[i] - rmax));
    lsum = ((ev[0] + ev[1]) + ev[2]) + ev[3];
    __syncthreads();
#pragma unroll
    for (int o = 16; o; o >>= 1) lsum += __shfl_xor_sync(0xffffffffu, lsum, o);
    if (lane == 0) sred[warp] = lsum;
    __syncthreads();
    float tot = 0.f;
#pragma unroll
    for (int jj = 0; jj < 8; jj++) tot += sred[jj];
    float inv = 1.0f / tot;
    *((float4*)(probs + (size_t)row * 1024) + t) =
        make_float4(ev[0] * inv, ev[1] * inv, ev[2] * inv, ev[3] * inv);

    // ---- top-5 (exact on z): ordered u32 keys ----
    unsigned cord[4]; unsigned cidx[4];
#pragma unroll
    for (int i = 0; i < 4; i++) {
        unsigned sb = __float_as_uint(zv[i]);
        cord[i] = (sb & 0x80000000u) ? ~sb : (sb | 0x80000000u);
        cidx[i] = (unsigned)((t << 2) + i);
    }
    __shared__ unsigned smo[40];
    __shared__ unsigned smi[40];
    __shared__ int si[5];
    __shared__ float sv[5];
    // warp-local top-5 (register-only, no barriers)
#pragma unroll
    for (int r5 = 0; r5 < 5; r5++) {
        unsigned bo = 0u, bi = 0xffffffffu;
#pragma unroll
        for (int i = 0; i < 4; i++)
            if (cord[i] > bo || (cord[i] == bo && cidx[i] < bi)) { bo = cord[i]; bi = cidx[i]; }
        unsigned wbo = redux_max_u32(bo);
        unsigned cand = (bo == wbo) ? bi : 0xffffffffu;
        unsigned wbi = redux_min_u32(cand);
        if (lane == 0) { smo[warp * 5 + r5] = wbo; smi[warp * 5 + r5] = wbi; }
#pragma unroll
        for (int i = 0; i < 4; i++)
            if (cidx[i] == wbi) cord[i] = 0u;
    }
    __syncthreads();
    // warp 0 merges the 40 candidates
    if (t < 32) {
        unsigned o1 = (t < 40) ? smo[t] : 0u;
        unsigned i1 = (t < 40) ? smi[t] : 0xffffffffu;
        unsigned o2 = (t + 32 < 40) ? smo[t + 32] : 0u;
        unsigned i2 = (t + 32 < 40) ? smi[t + 32] : 0xffffffffu;
#pragma unroll
        for (int r5 = 0; r5 < 5; r5++) {
            unsigned bo, bi;
            if (o1 > o2 || (o1 == o2 && i1 < i2)) { bo = o1; bi = i1; }
            else                                  { bo = o2; bi = i2; }
            unsigned wbo = redux_max_u32(bo);
            unsigned cand = (bo == wbo) ? bi : 0xffffffffu;
            unsigned wbi = redux_min_u32(cand);
            if (t == 0) si[r5] = (int)wbi;
            if (i1 == wbi) o1 = 0u;
            if (i2 == wbi) o2 = 0u;
        }
    }
    __syncthreads();
    if (t < 5) sv[t] = x[(row / 100) * 1024 + si[t]];
    __syncthreads();

    // ---- gather GEMV + synergy (same math/order as before) ----
    float s1 = sb1[t], y1 = yb1[t];
#pragma unroll
    for (int jj = 0; jj < 5; jj++) {
        int off = ((jj << 10) + si[jj]) << 8;   // (j*1024 + idx)*256
        float vj = sv[jj];
        s1 = fmaf(vj, sW1[off + t], s1);
        y1 = fmaf(vj, yW1[off + t], y1);
    }
    s1 = fmaxf(s1, 0.f);
    y1 = fmaxf(y1, 0.f);
    g_S1[((size_t)row << 8) + t] = s1;
    float c = y1 * yW2[t];
    __shared__ float rs[8];
#pragma unroll
    for (int o = 16; o; o >>= 1) c += __shfl_xor_sync(0xffffffffu, c, o);
    if (lane == 0) rs[warp] = c;
    __syncthreads();
    if (t == 0) {
        float tt = 0.f;
#pragma unroll
        for (int jj = 0; jj < 8; jj++) tt += rs[jj];
        out_syn[row] = tanhf(tt + yb2[0]);
    }
}

// =====================================================================
// K6: S2 = relu(S1 @ sW2 + sb2); score = sigmoid(S2 . sW3 + sb3)  (unchanged)
// =====================================================================
__global__ __launch_bounds__(256) void k_score(const float* __restrict__ W,
                                               const float* __restrict__ b2,
                                               const float* __restrict__ w3,
                                               const float* __restrict__ b3,
                                               float* __restrict__ out_scores)
{
    const int row0 = blockIdx.x << 5;          // 32 rows
    __shared__ float As[32][33];
    __shared__ __align__(16) float Bs[32][128];
    __shared__ float red[32][33];
    const int t  = threadIdx.x;
    const int tx = t & 31;
    const int ty = t >> 5;

    unsigned long long acc[4][2];
#pragma unroll
    for (int r = 0; r < 4; r++) { acc[r][0] = 0ULL; acc[r][1] = 0ULL; }

    for (int kk = 0; kk < 256; kk += 32) {
        {
            int r = t >> 3, k4 = t & 7;
            float4 v = *(const float4*)(g_S1 + (size_t)(row0 + r) * 256 + kk + (k4 << 2));
            As[r][(k4 << 2) + 0] = v.x;
            As[r][(k4 << 2) + 1] = v.y;
            As[r][(k4 << 2) + 2] = v.z;
            As[r][(k4 << 2) + 3] = v.w;
        }
#pragma unroll
        for (int i = 0; i < 4; i++) {
            int idx = t + (i << 8);
            int k = idx >> 5, n4 = idx & 31;
            *(float4*)&Bs[k][n4 << 2] = *(const float4*)(W + (kk + k) * 128 + (n4 << 2));
        }
        __syncthreads();
#pragma unroll
        for (int k = 0; k < 32; k++) {
            const ulonglong2 b01 = *(const ulonglong2*)&Bs[k][tx << 2];
#pragma unroll
            for (int r = 0; r < 4; r++) {
                unsigned long long aa;
                PACK2(aa, As[(ty << 2) + r][k]);
                FMA2(acc[r][0], aa, b01.x, acc[r][0]);
                FMA2(acc[r][1], aa, b01.y, acc[r][1]);
            }
        }
        __syncthreads();
    }

    float b2v[4], w3v[4];
#pragma unroll
    for (int c = 0; c < 4; c++) {
        b2v[c] = b2[(tx << 2) + c];
        w3v[c] = w3[(tx << 2) + c];
    }
#pragma unroll
    for (int r = 0; r < 4; r++) {
        float part = 0.f;
        {
            unsigned long long u = acc[r][0];
            float lo = __uint_as_float((unsigned)u);
            float hi = __uint_as_float((unsigned)(u >> 32));
            part += fmaxf(lo + b2v[0], 0.f) * w3v[0] + fmaxf(hi + b2v[1], 0.f) * w3v[1];
        }
        {
            unsigned long long u = acc[r][1];
            float lo = __uint_as_float((unsigned)u);
            float hi = __uint_as_float((unsigned)(u >> 32));
            part += fmaxf(lo + b2v[2], 0.f) * w3v[2] + fmaxf(hi + b2v[3], 0.f) * w3v[3];
        }
        red[(ty << 2) + r][tx] = part;
    }
    __syncthreads();
    if (t < 32) {
        float s = b3[0];
#pragma unroll
        for (int c = 0; c < 32; c++) s += red[t][c];
        out_scores[row0 + t] = 1.0f / (1.0f + __expf(-s));
    }
}

// =====================================================================
extern "C" void kernel_launch(void* const* d_in, const int* in_sizes, int n_in,
                              void* d_out, int out_size)
{
    (void)in_sizes; (void)n_in; (void)out_size;
    const float* x    = (const float*)d_in[0];
    const float* gum  = (const float*)d_in[1];
    const float* gW1  = (const float*)d_in[2];
    const float* gb1  = (const float*)d_in[3];
    const float* ln1s = (const float*)d_in[4];
    const float* ln1b = (const float*)d_in[5];
    const float* gW2  = (const float*)d_in[6];
    const float* gb2  = (const float*)d_in[7];
    const float* ln2s = (const float*)d_in[8];
    const float* ln2b = (const float*)d_in[9];
    const float* gW3  = (const float*)d_in[10];
    const float* gb3  = (const float*)d_in[11];
    const float* sW1  = (const float*)d_in[12];
    const float* sb1  = (const float*)d_in[13];
    const float* sW2  = (const float*)d_in[14];
    const float* sb2  = (const float*)d_in[15];
    const float* sW3  = (const float*)d_in[16];
    const float* sb3  = (const float*)d_in[17];
    const float* yW1  = (const float*)d_in[18];
    const float* yb1  = (const float*)d_in[19];
    const float* yW2  = (const float*)d_in[20];
    const float* yb2  = (const float*)d_in[21];

    float* out        = (float*)d_out;
    float* out_probs  = out;                       // [128,100,1024]
    float* out_scores = out + 13107200;            // [128,100]
    float* out_syn    = out + 13107200 + 12800;    // [128,100]
    float* out_logits = out + 13132800;            // [128,100,1024]

    k_gemm1ln1<<<32, 512>>>(x, gW1, gb1, ln1s, ln1b);          // 1
    k_gemm2<<<32, 256>>>(gW2, gb2);                             // 2
    k_ln2<<<128, 256>>>(ln2s, ln2b);                            // 3
    k_gemm3<<<400, 256>>>(gW3, gb3, out_logits);                // 4 <- ncu slot
    k_fused<<<12800, 256>>>(out_logits, gum, x, sW1, sb1,
                            yW1, yb1, yW2, yb2, out_probs, out_syn);  // 5
    k_score<<<400, 256>>>(sW2, sb2, sW3, sb3, out_scores);      // 6
}